// round 8
// baseline (speedup 1.0000x reference)
#include <cuda_runtime.h>
#include <cuda_fp16.h>
#include <cstdint>
#include <cstddef>

// Problem constants
#define B_   16
#define T_   8
#define KB_  64
#define CO_  128
#define CI_  128
#define H_   64
#define W_   64
#define WELEMS (CO_*CI_*25)          // 409600

// ---------------------------------------------------------------------------
// Scratch (__device__ globals; allocation-free rule)
// ---------------------------------------------------------------------------
__device__ __align__(16) unsigned g_xh[(size_t)B_*64*H_*W_];       // half2 x planes [b][ci/2][h][w]
__device__ __align__(16) __half  g_lph[(size_t)B_*8*2*CO_*25*8];   // [b][cc][kk][co][tap][ci8]

// ---------------------------------------------------------------------------
// Kernel P: fused prep (wsum blocks + xcvt blocks, concurrent).
// ---------------------------------------------------------------------------
#define NWB 512
#define NXB 512

__global__ __launch_bounds__(256) void k_prep(const float* __restrict__ x,
                                              const float* __restrict__ tf,
                                              const float* __restrict__ Wb) {
    const int blk = blockIdx.x;
    const int tid = threadIdx.x;

    if (blk < NWB) {
        // ---------------- wsum part ----------------
        __shared__ float ss[B_*KB_];
        __shared__ __align__(16) float wbuf[2][800];

        for (int i = tid; i < B_*KB_; i += 256) {
            int b = i >> 6, k = i & 63;
            float a = 0.f;
            #pragma unroll
            for (int t = 0; t < T_; t++) a += tf[(b*T_ + t)*KB_ + k];
            ss[i] = a * (1.0f / T_);
        }
        __syncthreads();

        const int co = blk >> 2;
        const int q  = blk & 3;               // ci quarter (32 ci)
        const bool act = tid < 200;
        const float* src = Wb + co*3200 + q*800 + 4*tid;

        float4 acc[B_];
        #pragma unroll
        for (int b = 0; b < B_; b++) acc[b] = make_float4(0.f, 0.f, 0.f, 0.f);

        if (act) {
            #pragma unroll 4
            for (int k = 0; k < KB_; k++) {
                float4 wv = *(const float4*)(src + (size_t)k*WELEMS);
                #pragma unroll
                for (int b = 0; b < B_; b++) {
                    float sv = ss[b*KB_ + k];
                    acc[b].x += sv * wv.x;
                    acc[b].y += sv * wv.y;
                    acc[b].z += sv * wv.z;
                    acc[b].w += sv * wv.w;
                }
            }
        }

        // transpose 2 examples per pass through smem; coalesced 16B stores
        const int bsel = tid / 100;           // 0/1 (tid<200)
        const int t2   = tid % 100;
        const int tap  = t2 % 25;
        const int c8   = t2 / 25;             // ci8-block within quarter (0..3)
        #pragma unroll 1
        for (int bp = 0; bp < 8; bp++) {
            if (act) {
                *(float4*)(wbuf[0] + 4*tid) = acc[2*bp];
                *(float4*)(wbuf[1] + 4*tid) = acc[2*bp + 1];
            }
            __syncthreads();
            if (tid < 200) {
                __half h[8];
                #pragma unroll
                for (int i2 = 0; i2 < 8; i2++)
                    h[i2] = __float2half_rn(wbuf[bsel][(c8*8 + i2)*25 + tap]);
                int b  = 2*bp + bsel;
                int cc = q*2 + (c8 >> 1);
                int kk = c8 & 1;
                size_t o = (((((size_t)b*8 + cc)*2 + kk)*CO_ + co)*25 + tap)*8;
                *(uint4*)(g_lph + o) = *(const uint4*)h;
            }
            __syncthreads();
        }
    } else {
        // ---------------- xcvt part ----------------
        const size_t total4 = (size_t)B_*64*H_*W_ / 4;     // uint4 count
        for (size_t e = (size_t)(blk - NWB)*256 + tid; e < total4;
             e += (size_t)NXB*256) {
            size_t i = e * 4;
            int hw   = (int)(i & 4095);
            int rest = (int)(i >> 12);
            int pl   = rest & 63;
            int b    = rest >> 6;
            const float* xb = x + ((size_t)(b*CI_ + 2*pl))*4096 + hw;
            float4 lo = *(const float4*)xb;
            float4 hi = *(const float4*)(xb + 4096);
            uint4 o;
            __half2 p0 = __floats2half2_rn(lo.x, hi.x);
            __half2 p1 = __floats2half2_rn(lo.y, hi.y);
            __half2 p2 = __floats2half2_rn(lo.z, hi.z);
            __half2 p3 = __floats2half2_rn(lo.w, hi.w);
            o.x = *(unsigned*)&p0; o.y = *(unsigned*)&p1;
            o.z = *(unsigned*)&p2; o.w = *(unsigned*)&p3;
            *(uint4*)(g_xh + i) = o;
        }
    }
}

// ---------------------------------------------------------------------------
// Kernel C: fp16 m16n8k16 conv.
// 256-thread CTA (8 warps), tile 64co x (4 rows x 64 px), warp 64co x 32px.
// Single smem buffer, 8 chunks of 16 ci; 2 CTAs/SM cover stage latency.
// ---------------------------------------------------------------------------
#define WS_TAPB   2048                     // bytes per tap slab (64co x 2 x 16B)
#define WS_BYTES  (25*WS_TAPB)             // 51200
#define XS_PLANE  584                      // words per ci-pair plane (8*72 + 8)
#define XS_WORDS  (8*XS_PLANE)             // 4672
#define SMEM_BYTES (WS_BYTES + XS_WORDS*4) // 69888

__device__ __forceinline__ void cp16(void* dst, const void* src) {
    unsigned d = (unsigned)__cvta_generic_to_shared(dst);
    asm volatile("cp.async.cg.shared.global [%0], [%1], 16;" :: "r"(d), "l"(src));
}
__device__ __forceinline__ void ldsm4(unsigned* r, unsigned addr) {
    asm volatile("ldmatrix.sync.aligned.m8n8.x4.shared.b16 {%0,%1,%2,%3}, [%4];"
                 : "=r"(r[0]), "=r"(r[1]), "=r"(r[2]), "=r"(r[3]) : "r"(addr));
}
__device__ __forceinline__ void mma16(float* d, const unsigned* a, const unsigned* bb) {
    asm volatile("mma.sync.aligned.m16n8k16.row.col.f32.f16.f16.f32 "
                 "{%0,%1,%2,%3}, {%4,%5,%6,%7}, {%8,%9}, {%0,%1,%2,%3};"
                 : "+f"(d[0]), "+f"(d[1]), "+f"(d[2]), "+f"(d[3])
                 : "r"(a[0]), "r"(a[1]), "r"(a[2]), "r"(a[3]), "r"(bb[0]), "r"(bb[1]));
}

__global__ __launch_bounds__(256, 2) void k_conv(float* __restrict__ y) {
    extern __shared__ __align__(128) unsigned char smem[];
    unsigned char* WS = smem;                       // swizzled weight slab
    unsigned*      XS = (unsigned*)(smem + WS_BYTES);

    const int tid = threadIdx.x;
    const int ln  = tid & 31;
    const int w   = tid >> 5;
    const int g   = ln >> 2;
    const int tig = ln & 3;
    const int wr  = w >> 1;              // output row within tile (0..3)
    const int cw  = (w & 1) * 32;        // column half

    const int h0  = blockIdx.x * 4;
    const int co0 = blockIdx.y * 64;
    const int b   = blockIdx.z;

    const unsigned ws_s = (unsigned)__cvta_generic_to_shared(WS);
    const unsigned swzA = ((unsigned)(((ln & 15) << 1) | ((ln >> 4) ^ ((ln >> 2) & 1)))) << 4;

    // zero XS once: halo cols + OOB rows stay zero for all chunks
    for (int i = tid; i < XS_WORDS; i += 256) XS[i] = 0;

    float acc[4][4][4];
    #pragma unroll
    for (int mf = 0; mf < 4; mf++)
        #pragma unroll
        for (int f = 0; f < 4; f++)
            #pragma unroll
            for (int r = 0; r < 4; r++) acc[mf][f][r] = 0.f;

    __syncthreads();

    #pragma unroll 1
    for (int cc = 0; cc < 8; cc++) {
        // ---- stage weights: 3200 x 16B ----
        #pragma unroll 1
        for (int e = tid; e < 3200; e += 256) {
            int kk  = e / 1600;
            int r   = e - kk*1600;
            int co  = r / 25;
            int tap = r - co*25;
            const __half* src = g_lph +
                (((((size_t)b*8 + cc)*2 + kk)*CO_ + co0 + co)*25 + tap)*8;
            int swz = (co*2 + (kk ^ ((co >> 2) & 1)))*16;
            cp16(WS + tap*WS_TAPB + swz, src);
        }
        // ---- stage x planes: 8 planes x 8 halo rows x 16 quads ----
        #pragma unroll 1
        for (int e = tid; e < 1024; e += 256) {
            int pl  = e >> 7;
            int rem = e & 127;
            int r   = rem >> 4;
            int qd  = rem & 15;
            int gh  = h0 - 2 + r;
            if ((unsigned)gh < H_) {
                const unsigned* src = g_xh + (((size_t)(b*64 + cc*8 + pl)*64 + gh) << 6) + qd*4;
                cp16(XS + pl*XS_PLANE + r*72 + 4 + qd*4, src);
            }
        }
        asm volatile("cp.async.commit_group;");
        asm volatile("cp.async.wait_group 0;");
        __syncthreads();

        const int xbase = wr*72 + 2 + cw + g;
        #pragma unroll
        for (int dh = 0; dh < 5; dh++) {
            #pragma unroll
            for (int dw = 0; dw < 5; dw++) {
                const int tap = dh*5 + dw;
                unsigned a[4][4];
                #pragma unroll
                for (int mf = 0; mf < 4; mf++)
                    ldsm4(a[mf], ws_s + tap*WS_TAPB + swzA + mf*512);

                unsigned bb[4][2];
                const int xo = xbase + dh*72 + dw;
                #pragma unroll
                for (int f = 0; f < 4; f++) {
                    bb[f][0] = XS[tig*XS_PLANE       + xo + 8*f];
                    bb[f][1] = XS[(tig + 4)*XS_PLANE + xo + 8*f];
                }
                #pragma unroll
                for (int mf = 0; mf < 4; mf++)
                    #pragma unroll
                    for (int f = 0; f < 4; f++)
                        mma16(acc[mf][f], a[mf], bb[f]);
            }
        }
        __syncthreads();
    }

    // epilogue
    const int hw = h0 + wr;
    #pragma unroll
    for (int mf = 0; mf < 4; mf++) {
        #pragma unroll
        for (int f = 0; f < 4; f++) {
            int co = co0 + 16*mf + g;
            int px = cw + 8*f + 2*tig;
            float* yp = y + (((size_t)b*CO_ + co)*H_ + hw)*W_ + px;
            *(float2*)yp             = make_float2(acc[mf][f][0], acc[mf][f][1]);
            *(float2*)(yp + 8*H_*W_) = make_float2(acc[mf][f][2], acc[mf][f][3]);
        }
    }
}

// ---------------------------------------------------------------------------
// Launch
// ---------------------------------------------------------------------------
extern "C" void kernel_launch(void* const* d_in, const int* in_sizes, int n_in,
                              void* d_out, int out_size) {
    const float* x  = (const float*)d_in[0];
    const float* tf = (const float*)d_in[1];
    const float* Wb = (const float*)d_in[2];
    float* y        = (float*)d_out;

    cudaFuncSetAttribute(k_conv, cudaFuncAttributeMaxDynamicSharedMemorySize, SMEM_BYTES);

    k_prep<<<NWB + NXB, 256>>>(x, tf, Wb);
    dim3 grid(16, 2, B_);
    k_conv<<<grid, 256, SMEM_BYTES>>>(y);
    (void)in_sizes; (void)n_in; (void)out_size;
}

// round 10
// speedup vs baseline: 1.0125x; 1.0125x over previous
#include <cuda_runtime.h>
#include <cuda_fp16.h>
#include <cstdint>
#include <cstddef>

#define B_   16
#define T_   8
#define KB_  64
#define CO_  128
#define CI_  128
#define H_   64
#define W_   64
#define WELEMS (CO_*CI_*25)

// ---------------------------------------------------------------------------
// Scratch (__device__ globals; allocation-free rule)
// ---------------------------------------------------------------------------
__device__ __align__(16) unsigned g_xh[(size_t)B_*64*H_*W_];     // half2 x planes [b][ci/2][h][w]
// weights: [b][chunk8][coh2] blocks of 25600 halves: [kk2][co64][tap25][ci8]
__device__ __align__(16) __half g_lphB[(size_t)B_*8*2*25600];

// ---------------------------------------------------------------------------
// Kernel P: fused prep (wsum blocks + xcvt blocks, concurrent).
// ---------------------------------------------------------------------------
#define NWB 512
#define NXB 512

__global__ __launch_bounds__(256) void k_prep(const float* __restrict__ x,
                                              const float* __restrict__ tf,
                                              const float* __restrict__ Wb) {
    const int blk = blockIdx.x;
    const int tid = threadIdx.x;

    if (blk < NWB) {
        // ---------------- wsum ----------------
        __shared__ float ss[B_*KB_];
        __shared__ __align__(16) float wbuf[2][800];

        for (int i = tid; i < B_*KB_; i += 256) {
            int b = i >> 6, k = i & 63;
            float a = 0.f;
            #pragma unroll
            for (int t = 0; t < T_; t++) a += tf[(b*T_ + t)*KB_ + k];
            ss[i] = a * (1.0f / T_);
        }
        __syncthreads();

        const int co = blk >> 2;
        const int q  = blk & 3;               // ci quarter (32 ci)
        const bool act = tid < 200;
        const float* src = Wb + co*3200 + q*800 + 4*tid;

        float4 acc[B_];
        #pragma unroll
        for (int b = 0; b < B_; b++) acc[b] = make_float4(0.f, 0.f, 0.f, 0.f);

        if (act) {
            #pragma unroll 4
            for (int k = 0; k < KB_; k++) {
                float4 wv = *(const float4*)(src + (size_t)k*WELEMS);
                #pragma unroll
                for (int b = 0; b < B_; b++) {
                    float sv = ss[b*KB_ + k];
                    acc[b].x += sv * wv.x;
                    acc[b].y += sv * wv.y;
                    acc[b].z += sv * wv.z;
                    acc[b].w += sv * wv.w;
                }
            }
        }

        // transpose 2 examples per pass through smem; coalesced 16B stores
        const int bsel  = tid / 100;          // 0/1 (tid<200)
        const int t2    = tid % 100;
        const int tap   = t2 % 25;
        const int c8    = t2 / 25;            // ci8-block within quarter (0..3)
        const int chunk = 2*q + (c8 >> 1);    // ci16 chunk
        const int kk    = c8 & 1;
        const int coh   = co >> 6;
        const int c64   = co & 63;
        #pragma unroll 1
        for (int bp = 0; bp < 8; bp++) {
            if (act) {
                *(float4*)(wbuf[0] + 4*tid) = acc[2*bp];
                *(float4*)(wbuf[1] + 4*tid) = acc[2*bp + 1];
            }
            __syncthreads();
            if (tid < 200) {
                __half h[8];
                #pragma unroll
                for (int i2 = 0; i2 < 8; i2++)
                    h[i2] = __float2half_rn(wbuf[bsel][(c8*8 + i2)*25 + tap]);
                int b = 2*bp + bsel;
                size_t o = (((size_t)(b*8 + chunk)*2 + coh)*25600)
                         + (((size_t)kk*64 + c64)*25 + tap)*8;
                *(uint4*)(g_lphB + o) = *(const uint4*)h;
            }
            __syncthreads();
        }
    } else {
        // ---------------- xcvt ----------------
        const size_t total4 = (size_t)B_*64*H_*W_ / 4;
        for (size_t e = (size_t)(blk - NWB)*256 + tid; e < total4;
             e += (size_t)NXB*256) {
            size_t i = e * 4;
            int hw   = (int)(i & 4095);
            int rest = (int)(i >> 12);
            int pl   = rest & 63;
            int b    = rest >> 6;
            const float* xb = x + ((size_t)(b*CI_ + 2*pl))*4096 + hw;
            float4 lo = *(const float4*)xb;
            float4 hi = *(const float4*)(xb + 4096);
            uint4 o;
            __half2 p0 = __floats2half2_rn(lo.x, hi.x);
            __half2 p1 = __floats2half2_rn(lo.y, hi.y);
            __half2 p2 = __floats2half2_rn(lo.z, hi.z);
            __half2 p3 = __floats2half2_rn(lo.w, hi.w);
            o.x = *(unsigned*)&p0; o.y = *(unsigned*)&p1;
            o.z = *(unsigned*)&p2; o.w = *(unsigned*)&p3;
            *(uint4*)(g_xh + i) = o;
        }
    }
}

// ---------------------------------------------------------------------------
// Kernel C: fp16 m16n8k16 conv, cp.async.bulk staging + mbarrier.
// CTA 256 thr (8 warps), tile 64co x (4 rows x 64 px), warp 64co x 32px.
// Per ci16 chunk: 1 bulk weight copy (51200B) + <=64 bulk x-row copies (256B).
// ---------------------------------------------------------------------------
#define WS_OFF    1024
#define WS_BYTES  51200
#define XS_OFF    (WS_OFF + WS_BYTES)        // 52224
#define XS_PLANE  584                        // words per plane (8*72 + 8)
#define XS_WORDS  (8*XS_PLANE)               // 4672
#define SMEM_BYTES (XS_OFF + XS_WORDS*4)     // 70912

__device__ __forceinline__ void bulk(unsigned dst, const void* src, unsigned n, unsigned mb) {
    asm volatile("cp.async.bulk.shared::cta.global.mbarrier::complete_tx::bytes [%0], [%1], %2, [%3];"
                 :: "r"(dst), "l"(src), "r"(n), "r"(mb) : "memory");
}
__device__ __forceinline__ void mbwait(unsigned mb, unsigned par) {
    asm volatile("{\n\t.reg .pred P;\n\tWL%=:\n\t"
                 "mbarrier.try_wait.parity.acquire.cta.shared::cta.b64 P, [%0], %1, 0x989680;\n\t"
                 "@P bra.uni WD%=;\n\tbra.uni WL%=;\n\tWD%=:\n\t}"
                 :: "r"(mb), "r"(par) : "memory");
}
__device__ __forceinline__ void ldsm4(unsigned* r, unsigned addr) {
    asm volatile("ldmatrix.sync.aligned.m8n8.x4.shared.b16 {%0,%1,%2,%3}, [%4];"
                 : "=r"(r[0]), "=r"(r[1]), "=r"(r[2]), "=r"(r[3]) : "r"(addr));
}
__device__ __forceinline__ void mma16(float* d, const unsigned* a, const unsigned* bb) {
    asm volatile("mma.sync.aligned.m16n8k16.row.col.f32.f16.f16.f32 "
                 "{%0,%1,%2,%3}, {%4,%5,%6,%7}, {%8,%9}, {%0,%1,%2,%3};"
                 : "+f"(d[0]), "+f"(d[1]), "+f"(d[2]), "+f"(d[3])
                 : "r"(a[0]), "r"(a[1]), "r"(a[2]), "r"(a[3]), "r"(bb[0]), "r"(bb[1]));
}

__global__ __launch_bounds__(256, 2) void k_conv(float* __restrict__ y) {
    extern __shared__ __align__(128) unsigned char smem[];
    const unsigned sb = (unsigned)__cvta_generic_to_shared(smem);
    unsigned* XS = (unsigned*)(smem + XS_OFF);

    const int tid = threadIdx.x;
    const int ln  = tid & 31;
    const int w   = tid >> 5;
    const int g   = ln >> 2;
    const int tig = ln & 3;
    const int wr  = w >> 1;              // output row within tile (0..3)
    const int cw  = (w & 1) * 32;        // column half

    const int h0  = blockIdx.x * 4;
    const int coh = blockIdx.y;          // co half (0/1)
    const int b   = blockIdx.z;

    // raw (no-swizzle) ldmatrix base: row (kk,co64,tap) at ((kk*64+co64)*25+tap)*16B
    const unsigned aBase = sb + WS_OFF + ((unsigned)((ln >> 4)*64 + (ln & 15)))*400u;

    // zero XS once: halo cols + OOB rows stay zero
    for (int i = tid; i < XS_WORDS; i += 256) XS[i] = 0;
    if (tid == 0)
        asm volatile("mbarrier.init.shared.b64 [%0], 1;" :: "r"(sb) : "memory");

    const int rlo = (h0 == 0)  ? 2 : 0;
    const int rhi = (h0 == 60) ? 6 : 8;
    const unsigned xtx = (unsigned)(WS_BYTES + (rhi - rlo)*8*256);

    float acc[4][4][4];
    #pragma unroll
    for (int mf = 0; mf < 4; mf++)
        #pragma unroll
        for (int f = 0; f < 4; f++)
            #pragma unroll
            for (int r = 0; r < 4; r++) acc[mf][f][r] = 0.f;

    __syncthreads();

    #pragma unroll 1
    for (int cc = 0; cc < 8; cc++) {
        __syncthreads();                 // previous compute done before overwrite
        if (tid == 0) {
            asm volatile("mbarrier.arrive.expect_tx.shared.b64 _, [%0], %1;"
                         :: "r"(sb), "r"(xtx) : "memory");
            bulk(sb + WS_OFF,
                 g_lphB + ((size_t)(b*8 + cc)*2 + coh)*25600, WS_BYTES, sb);
            #pragma unroll 1
            for (int pl = 0; pl < 8; pl++)
                for (int r = rlo; r < rhi; r++)
                    bulk(sb + XS_OFF + (unsigned)(pl*XS_PLANE + r*72 + 4)*4,
                         g_xh + (((size_t)(b*64 + cc*8 + pl)*64) + h0 - 2 + r)*64,
                         256, sb);
        }
        mbwait(sb, cc & 1);

        const int xbase = wr*72 + 2 + cw + g;
        #pragma unroll
        for (int dh = 0; dh < 5; dh++) {
            #pragma unroll
            for (int dw = 0; dw < 5; dw++) {
                const int tap = dh*5 + dw;
                unsigned a[4][4];
                #pragma unroll
                for (int mf = 0; mf < 4; mf++)
                    ldsm4(a[mf], aBase + mf*6400 + tap*16);

                unsigned bb[4][2];
                const int xo = xbase + dh*72 + dw;
                #pragma unroll
                for (int f = 0; f < 4; f++) {
                    bb[f][0] = XS[tig*XS_PLANE       + xo + 8*f];
                    bb[f][1] = XS[(tig + 4)*XS_PLANE + xo + 8*f];
                }
                #pragma unroll
                for (int mf = 0; mf < 4; mf++)
                    #pragma unroll
                    for (int f = 0; f < 4; f++)
                        mma16(acc[mf][f], a[mf], bb[f]);
            }
        }
    }

    // epilogue
    const int hw = h0 + wr;
    #pragma unroll
    for (int mf = 0; mf < 4; mf++) {
        #pragma unroll
        for (int f = 0; f < 4; f++) {
            int co = coh*64 + 16*mf + g;
            int px = cw + 8*f + 2*tig;
            float* yp = y + (((size_t)b*CO_ + co)*H_ + hw)*W_ + px;
            *(float2*)yp             = make_float2(acc[mf][f][0], acc[mf][f][1]);
            *(float2*)(yp + 8*H_*W_) = make_float2(acc[mf][f][2], acc[mf][f][3]);
        }
    }
}

// ---------------------------------------------------------------------------
// Launch
// ---------------------------------------------------------------------------
extern "C" void kernel_launch(void* const* d_in, const int* in_sizes, int n_in,
                              void* d_out, int out_size) {
    const float* x  = (const float*)d_in[0];
    const float* tf = (const float*)d_in[1];
    const float* Wb = (const float*)d_in[2];
    float* y        = (float*)d_out;

    cudaFuncSetAttribute(k_conv, cudaFuncAttributeMaxDynamicSharedMemorySize, SMEM_BYTES);

    k_prep<<<NWB + NXB, 256>>>(x, tf, Wb);
    dim3 grid(16, 2, B_);
    k_conv<<<grid, 256, SMEM_BYTES>>>(y);
    (void)in_sizes; (void)n_in; (void)out_size;
}

// round 12
// speedup vs baseline: 1.1932x; 1.1785x over previous
#include <cuda_runtime.h>
#include <cuda_fp16.h>
#include <cstdint>
#include <cstddef>

#define B_   16
#define T_   8
#define KB_  64
#define CO_  128
#define CI_  128
#define H_   64
#define W_   64
#define WELEMS (CO_*CI_*25)

// ---------------------------------------------------------------------------
// Scratch (__device__ globals; zero-initialized, allocation-free rule)
// ---------------------------------------------------------------------------
// padded half2 x planes: [b][pl64][row68][word72]; image row h -> row h+2,
// px p -> word p+4. Halo rows/cols stay zero (never written).
__device__ __align__(16) unsigned g_xh[(size_t)B_*64*68*72];
// weights: [b][chunk8][coh2] contiguous 51200B blocks: [kk2][co64][tap25][ci8]
__device__ __align__(16) __half g_lphB[(size_t)B_*8*2*25600];

// ---------------------------------------------------------------------------
// Kernel P: fused prep (wsum blocks + xcvt blocks, concurrent).
// ---------------------------------------------------------------------------
#define NWB 512
#define NXB 512

__global__ __launch_bounds__(256) void k_prep(const float* __restrict__ x,
                                              const float* __restrict__ tf,
                                              const float* __restrict__ Wb) {
    const int blk = blockIdx.x;
    const int tid = threadIdx.x;

    if (blk < NWB) {
        // ---------------- wsum ----------------
        __shared__ float ss[B_*KB_];
        __shared__ __align__(16) float wbuf[2][800];

        for (int i = tid; i < B_*KB_; i += 256) {
            int b = i >> 6, k = i & 63;
            float a = 0.f;
            #pragma unroll
            for (int t = 0; t < T_; t++) a += tf[(b*T_ + t)*KB_ + k];
            ss[i] = a * (1.0f / T_);
        }
        __syncthreads();

        const int co = blk >> 2;
        const int q  = blk & 3;               // ci quarter (32 ci)
        const bool act = tid < 200;
        const float* src = Wb + co*3200 + q*800 + 4*tid;

        float4 acc[B_];
        #pragma unroll
        for (int b = 0; b < B_; b++) acc[b] = make_float4(0.f, 0.f, 0.f, 0.f);

        if (act) {
            #pragma unroll 4
            for (int k = 0; k < KB_; k++) {
                float4 wv = *(const float4*)(src + (size_t)k*WELEMS);
                #pragma unroll
                for (int b = 0; b < B_; b++) {
                    float sv = ss[b*KB_ + k];
                    acc[b].x += sv * wv.x;
                    acc[b].y += sv * wv.y;
                    acc[b].z += sv * wv.z;
                    acc[b].w += sv * wv.w;
                }
            }
        }

        const int bsel  = tid / 100;
        const int t2    = tid % 100;
        const int tap   = t2 % 25;
        const int c8    = t2 / 25;            // ci8-block within quarter
        const int chunk = 2*q + (c8 >> 1);
        const int kk    = c8 & 1;
        const int coh   = co >> 6;
        const int c64   = co & 63;
        #pragma unroll 1
        for (int bp = 0; bp < 8; bp++) {
            if (act) {
                *(float4*)(wbuf[0] + 4*tid) = acc[2*bp];
                *(float4*)(wbuf[1] + 4*tid) = acc[2*bp + 1];
            }
            __syncthreads();
            if (tid < 200) {
                __half h[8];
                #pragma unroll
                for (int i2 = 0; i2 < 8; i2++)
                    h[i2] = __float2half_rn(wbuf[bsel][(c8*8 + i2)*25 + tap]);
                int b = 2*bp + bsel;
                size_t o = (((size_t)(b*8 + chunk)*2 + coh)*25600)
                         + (((size_t)kk*64 + c64)*25 + tap)*8;
                *(uint4*)(g_lphB + o) = *(const uint4*)h;
            }
            __syncthreads();
        }
    } else {
        // ---------------- xcvt: write padded planes (interior only) --------
        const size_t total4 = (size_t)B_*64*H_*W_ / 4;   // quads of half2
        for (size_t e = (size_t)(blk - NWB)*256 + tid; e < total4;
             e += (size_t)NXB*256) {
            size_t i = e * 4;
            int px   = (int)(i & 63);
            int rest = (int)(i >> 6);
            int h    = rest & 63;
            int pr   = rest >> 6;
            int pl   = pr & 63;
            int b    = pr >> 6;
            const float* xb = x + ((size_t)(b*CI_ + 2*pl)*H_ + h)*W_ + px;
            float4 lo = *(const float4*)xb;
            float4 hi = *(const float4*)(xb + H_*W_);
            uint4 o;
            __half2 p0 = __floats2half2_rn(lo.x, hi.x);
            __half2 p1 = __floats2half2_rn(lo.y, hi.y);
            __half2 p2 = __floats2half2_rn(lo.z, hi.z);
            __half2 p3 = __floats2half2_rn(lo.w, hi.w);
            o.x = *(unsigned*)&p0; o.y = *(unsigned*)&p1;
            o.z = *(unsigned*)&p2; o.w = *(unsigned*)&p3;
            size_t dst = ((size_t)(b*64 + pl)*68 + h + 2)*72 + px + 4;
            *(uint4*)(g_xh + dst) = o;
        }
    }
}

// ---------------------------------------------------------------------------
// Kernel C: fp16 m16n8k16 conv, double-buffered cp.async.bulk pipeline.
// 512 thr (16 warps), 1 CTA/SM. Tile 64co x (8 rows x 64 px); warp 64co x 32px.
// Per ci16 chunk: 1 weight bulk (51200B) + 8 plane bulks (3456B).
// ---------------------------------------------------------------------------
#define WS0_OFF   1024
#define WS_BYTES  51200
#define XS0_OFF   (WS0_OFF + 2*WS_BYTES)          // 103424
#define XS_PLANE  872                             // words per plane (12*72 + 8)
#define XS_BYTES  (8*XS_PLANE*4)                  // 27904
#define SMEM_BYTES (XS0_OFF + 2*XS_BYTES)         // 159232
#define TX_BYTES  (WS_BYTES + 8*3456)             // 78848

__device__ __forceinline__ void bulk(unsigned dst, const void* src, unsigned n, unsigned mb) {
    asm volatile("cp.async.bulk.shared::cta.global.mbarrier::complete_tx::bytes [%0], [%1], %2, [%3];"
                 :: "r"(dst), "l"(src), "r"(n), "r"(mb) : "memory");
}
__device__ __forceinline__ void mbwait(unsigned mb, unsigned par) {
    asm volatile("{\n\t.reg .pred P;\n\tWL%=:\n\t"
                 "mbarrier.try_wait.parity.acquire.cta.shared::cta.b64 P, [%0], %1, 0x989680;\n\t"
                 "@P bra.uni WD%=;\n\tbra.uni WL%=;\n\tWD%=:\n\t}"
                 :: "r"(mb), "r"(par) : "memory");
}
__device__ __forceinline__ void ldsm4(unsigned* r, unsigned addr) {
    asm volatile("ldmatrix.sync.aligned.m8n8.x4.shared.b16 {%0,%1,%2,%3}, [%4];"
                 : "=r"(r[0]), "=r"(r[1]), "=r"(r[2]), "=r"(r[3]) : "r"(addr));
}
__device__ __forceinline__ void mma16(float* d, const unsigned* a, const unsigned* bb) {
    asm volatile("mma.sync.aligned.m16n8k16.row.col.f32.f16.f16.f32 "
                 "{%0,%1,%2,%3}, {%4,%5,%6,%7}, {%8,%9}, {%0,%1,%2,%3};"
                 : "+f"(d[0]), "+f"(d[1]), "+f"(d[2]), "+f"(d[3])
                 : "r"(a[0]), "r"(a[1]), "r"(a[2]), "r"(a[3]), "r"(bb[0]), "r"(bb[1]));
}

__global__ __launch_bounds__(512, 1) void k_conv(float* __restrict__ y) {
    extern __shared__ __align__(128) unsigned char smem[];
    const unsigned sb = (unsigned)__cvta_generic_to_shared(smem);

    const int tid = threadIdx.x;
    const int ln  = tid & 31;
    const int w   = tid >> 5;
    const int g   = ln >> 2;
    const int tig = ln & 3;
    const int wr  = w >> 1;              // output row within tile (0..7)
    const int cw  = (w & 1) * 32;        // column half

    const int h0  = blockIdx.x * 8;
    const int coh = blockIdx.y;
    const int b   = blockIdx.z;

    // raw ldmatrix base within weight slab: row (kk,co64) at stride 400B
    const unsigned aLane = ((unsigned)((ln >> 4)*64 + (ln & 15)))*400u;

    if (tid == 0) {
        asm volatile("mbarrier.init.shared.b64 [%0], 1;" :: "r"(sb+0) : "memory");
        asm volatile("mbarrier.init.shared.b64 [%0], 1;" :: "r"(sb+8) : "memory");
    }
    __syncthreads();

    // stage chunk cs into buffer bufi (thread 0 only)
    auto stage = [&](int cs, int bufi) {
        unsigned mb = sb + bufi*8;
        asm volatile("mbarrier.arrive.expect_tx.shared.b64 _, [%0], %1;"
                     :: "r"(mb), "r"((unsigned)TX_BYTES) : "memory");
        bulk(sb + WS0_OFF + bufi*WS_BYTES,
             g_lphB + ((size_t)(b*8 + cs)*2 + coh)*25600, WS_BYTES, mb);
        #pragma unroll
        for (int pl = 0; pl < 8; pl++)
            bulk(sb + XS0_OFF + bufi*XS_BYTES + pl*(XS_PLANE*4),
                 g_xh + ((size_t)(b*64 + cs*8 + pl)*68 + h0)*72,
                 3456, mb);
    };

    float acc[4][4][4];
    #pragma unroll
    for (int mf = 0; mf < 4; mf++)
        #pragma unroll
        for (int f = 0; f < 4; f++)
            #pragma unroll
            for (int r = 0; r < 4; r++) acc[mf][f][r] = 0.f;

    if (tid == 0) { stage(0, 0); stage(1, 1); }

    #pragma unroll 1
    for (int cc = 0; cc < 8; cc++) {
        const int bufi = cc & 1;
        mbwait(sb + bufi*8, (cc >> 1) & 1);

        const unsigned  aBase = sb + WS0_OFF + bufi*WS_BYTES + aLane;
        const unsigned* XS    = (const unsigned*)(smem + XS0_OFF + bufi*XS_BYTES);
        const int xbase = (wr)*72 + 2 + cw + g;

        #pragma unroll
        for (int dh = 0; dh < 5; dh++) {
            #pragma unroll
            for (int dw = 0; dw < 5; dw++) {
                const int tap = dh*5 + dw;
                unsigned a[4][4];
                #pragma unroll
                for (int mf = 0; mf < 4; mf++)
                    ldsm4(a[mf], aBase + mf*6400 + tap*16);

                unsigned bb[4][2];
                const int xo = xbase + dh*72 + dw;
                #pragma unroll
                for (int f = 0; f < 4; f++) {
                    bb[f][0] = XS[tig*XS_PLANE       + xo + 8*f];
                    bb[f][1] = XS[(tig + 4)*XS_PLANE + xo + 8*f];
                }
                #pragma unroll
                for (int mf = 0; mf < 4; mf++)
                    #pragma unroll
                    for (int f = 0; f < 4; f++)
                        mma16(acc[mf][f], a[mf], bb[f]);
            }
        }

        __syncthreads();                   // all warps done with this buffer
        if (cc < 6 && tid == 0) stage(cc + 2, bufi);
    }

    // epilogue
    const int hw = h0 + wr;
    #pragma unroll
    for (int mf = 0; mf < 4; mf++) {
        #pragma unroll
        for (int f = 0; f < 4; f++) {
            int co = coh*64 + 16*mf + g;
            int px = cw + 8*f + 2*tig;
            float* yp = y + (((size_t)b*CO_ + co)*H_ + hw)*W_ + px;
            *(float2*)yp             = make_float2(acc[mf][f][0], acc[mf][f][1]);
            *(float2*)(yp + 8*H_*W_) = make_float2(acc[mf][f][2], acc[mf][f][3]);
        }
    }
}

// ---------------------------------------------------------------------------
// Launch
// ---------------------------------------------------------------------------
extern "C" void kernel_launch(void* const* d_in, const int* in_sizes, int n_in,
                              void* d_out, int out_size) {
    const float* x  = (const float*)d_in[0];
    const float* tf = (const float*)d_in[1];
    const float* Wb = (const float*)d_in[2];
    float* y        = (float*)d_out;

    cudaFuncSetAttribute(k_conv, cudaFuncAttributeMaxDynamicSharedMemorySize, SMEM_BYTES);

    k_prep<<<NWB + NXB, 256>>>(x, tf, Wb);
    dim3 grid(8, 2, B_);
    k_conv<<<grid, 512, SMEM_BYTES>>>(y);
    (void)in_sizes; (void)n_in; (void)out_size;
}

// round 13
// speedup vs baseline: 1.2932x; 1.0838x over previous
#include <cuda_runtime.h>
#include <cuda_fp16.h>
#include <cstdint>
#include <cstddef>

#define B_   16
#define T_   8
#define KB_  64
#define CO_  128
#define CI_  128
#define H_   64
#define W_   64
#define WELEMS (CO_*CI_*25)

// ---------------------------------------------------------------------------
// Scratch (__device__ globals; zero-initialized, allocation-free rule)
// ---------------------------------------------------------------------------
// padded half2 x planes: [b][pl64][row68][word72]; image row h -> row h+2,
// px p -> word p+4. Halo rows/cols stay zero (never written).
__device__ __align__(16) unsigned g_xh[(size_t)B_*64*68*72];
// weights: [b][chunk8][coh2] contiguous 51200B blocks: [kk2][co64][tap25][ci8]
__device__ __align__(16) __half g_lphB[(size_t)B_*8*2*25600];

// ---------------------------------------------------------------------------
// packed f32x2 helpers (Blackwell FFMA2 path)
// ---------------------------------------------------------------------------
__device__ __forceinline__ unsigned long long ffma2(unsigned long long a,
                                                    unsigned long long b,
                                                    unsigned long long c) {
    unsigned long long d;
    asm("fma.rn.f32x2 %0, %1, %2, %3;" : "=l"(d) : "l"(a), "l"(b), "l"(c));
    return d;
}
__device__ __forceinline__ unsigned long long packdup(float v) {
    unsigned long long o; unsigned u = __float_as_uint(v);
    asm("mov.b64 %0, {%1, %2};" : "=l"(o) : "r"(u), "r"(u));
    return o;
}
__device__ __forceinline__ void unpack2(float& lo, float& hi, unsigned long long v) {
    unsigned a, b;
    asm("mov.b64 {%0, %1}, %2;" : "=r"(a), "=r"(b) : "l"(v));
    lo = __uint_as_float(a); hi = __uint_as_float(b);
}

// ---------------------------------------------------------------------------
// Kernel P: fused prep (wsum blocks + xcvt blocks, concurrent).
// ---------------------------------------------------------------------------
#define NWB 512
#define NXB 512

__global__ __launch_bounds__(256) void k_prep(const float* __restrict__ x,
                                              const float* __restrict__ tf,
                                              const float* __restrict__ Wb) {
    const int blk = blockIdx.x;
    const int tid = threadIdx.x;

    if (blk < NWB) {
        // ---------------- wsum (FFMA2, b-pairs packed) ----------------
        __shared__ __align__(8)  float sst[64][16];   // [k][b] transposed
        __shared__ __align__(16) float wbuf[2][800];

        for (int i = tid; i < B_*KB_; i += 256) {
            int b = i >> 6, k = i & 63;
            float a = 0.f;
            #pragma unroll
            for (int t = 0; t < T_; t++) a += tf[(b*T_ + t)*KB_ + k];
            sst[k][b] = a * (1.0f / T_);
        }
        __syncthreads();

        const int co = blk >> 2;
        const int q  = blk & 3;               // ci quarter (32 ci)
        const bool act = tid < 200;
        const float* src = Wb + co*3200 + q*800 + 4*tid;

        unsigned long long accp[8][4];        // [b-pair][component]
        #pragma unroll
        for (int i = 0; i < 8; i++)
            #pragma unroll
            for (int c = 0; c < 4; c++) accp[i][c] = 0ull;

        if (act) {
            #pragma unroll 4
            for (int k = 0; k < KB_; k++) {
                float4 wv = *(const float4*)(src + (size_t)k*WELEMS);
                unsigned long long wx = packdup(wv.x), wy = packdup(wv.y);
                unsigned long long wz = packdup(wv.z), ww = packdup(wv.w);
                const unsigned long long* sp = (const unsigned long long*)&sst[k][0];
                #pragma unroll
                for (int i = 0; i < 8; i++) {
                    unsigned long long s2 = sp[i];       // {s[2i], s[2i+1]} broadcast
                    accp[i][0] = ffma2(s2, wx, accp[i][0]);
                    accp[i][1] = ffma2(s2, wy, accp[i][1]);
                    accp[i][2] = ffma2(s2, wz, accp[i][2]);
                    accp[i][3] = ffma2(s2, ww, accp[i][3]);
                }
            }
        }

        const int bsel  = tid / 100;
        const int t2    = tid % 100;
        const int tap   = t2 % 25;
        const int c8    = t2 / 25;            // ci8-block within quarter
        const int chunk = 2*q + (c8 >> 1);
        const int kk    = c8 & 1;
        const int coh   = co >> 6;
        const int c64   = co & 63;
        #pragma unroll 1
        for (int bp = 0; bp < 8; bp++) {
            if (act) {
                float4 a0, a1;
                unpack2(a0.x, a1.x, accp[bp][0]);
                unpack2(a0.y, a1.y, accp[bp][1]);
                unpack2(a0.z, a1.z, accp[bp][2]);
                unpack2(a0.w, a1.w, accp[bp][3]);
                *(float4*)(wbuf[0] + 4*tid) = a0;
                *(float4*)(wbuf[1] + 4*tid) = a1;
            }
            __syncthreads();
            if (tid < 200) {
                __half h[8];
                #pragma unroll
                for (int i2 = 0; i2 < 8; i2++)
                    h[i2] = __float2half_rn(wbuf[bsel][(c8*8 + i2)*25 + tap]);
                int b = 2*bp + bsel;
                size_t o = (((size_t)(b*8 + chunk)*2 + coh)*25600)
                         + (((size_t)kk*64 + c64)*25 + tap)*8;
                *(uint4*)(g_lphB + o) = *(const uint4*)h;
            }
            __syncthreads();
        }
    } else {
        // ---------------- xcvt: write padded planes (interior only) --------
        const size_t total4 = (size_t)B_*64*H_*W_ / 4;
        for (size_t e = (size_t)(blk - NWB)*256 + tid; e < total4;
             e += (size_t)NXB*256) {
            size_t i = e * 4;
            int px   = (int)(i & 63);
            int rest = (int)(i >> 6);
            int h    = rest & 63;
            int pr   = rest >> 6;
            int pl   = pr & 63;
            int b    = pr >> 6;
            const float* xb = x + ((size_t)(b*CI_ + 2*pl)*H_ + h)*W_ + px;
            float4 lo = *(const float4*)xb;
            float4 hi = *(const float4*)(xb + H_*W_);
            uint4 o;
            __half2 p0 = __floats2half2_rn(lo.x, hi.x);
            __half2 p1 = __floats2half2_rn(lo.y, hi.y);
            __half2 p2 = __floats2half2_rn(lo.z, hi.z);
            __half2 p3 = __floats2half2_rn(lo.w, hi.w);
            o.x = *(unsigned*)&p0; o.y = *(unsigned*)&p1;
            o.z = *(unsigned*)&p2; o.w = *(unsigned*)&p3;
            size_t dst = ((size_t)(b*64 + pl)*68 + h + 2)*72 + px + 4;
            *(uint4*)(g_xh + dst) = o;
        }
    }
}

// ---------------------------------------------------------------------------
// Kernel C: fp16 m16n8k16 conv, double-buffered cp.async.bulk pipeline with
// full/empty mbarriers (no per-chunk __syncthreads).
// 512 thr (16 warps), 1 CTA/SM. Tile 64co x (8 rows x 64 px); warp 64co x 32px.
// ---------------------------------------------------------------------------
#define WS0_OFF   1024
#define WS_BYTES  51200
#define XS0_OFF   (WS0_OFF + 2*WS_BYTES)          // 103424
#define XS_PLANE  872                             // words per plane (12*72 + 8)
#define XS_BYTES  (8*XS_PLANE*4)                  // 27904
#define SMEM_BYTES (XS0_OFF + 2*XS_BYTES)         // 159232
#define TX_BYTES  (WS_BYTES + 8*3456)             // 78848

__device__ __forceinline__ void bulk(unsigned dst, const void* src, unsigned n, unsigned mb) {
    asm volatile("cp.async.bulk.shared::cta.global.mbarrier::complete_tx::bytes [%0], [%1], %2, [%3];"
                 :: "r"(dst), "l"(src), "r"(n), "r"(mb) : "memory");
}
__device__ __forceinline__ void mbwait(unsigned mb, unsigned par) {
    asm volatile("{\n\t.reg .pred P;\n\tWL%=:\n\t"
                 "mbarrier.try_wait.parity.acquire.cta.shared::cta.b64 P, [%0], %1, 0x989680;\n\t"
                 "@P bra.uni WD%=;\n\tbra.uni WL%=;\n\tWD%=:\n\t}"
                 :: "r"(mb), "r"(par) : "memory");
}
__device__ __forceinline__ void mbarrive(unsigned mb) {
    asm volatile("mbarrier.arrive.shared.b64 _, [%0];" :: "r"(mb) : "memory");
}
__device__ __forceinline__ void ldsm4(unsigned* r, unsigned addr) {
    asm volatile("ldmatrix.sync.aligned.m8n8.x4.shared.b16 {%0,%1,%2,%3}, [%4];"
                 : "=r"(r[0]), "=r"(r[1]), "=r"(r[2]), "=r"(r[3]) : "r"(addr));
}
__device__ __forceinline__ void mma16(float* d, const unsigned* a, const unsigned* bb) {
    asm volatile("mma.sync.aligned.m16n8k16.row.col.f32.f16.f16.f32 "
                 "{%0,%1,%2,%3}, {%4,%5,%6,%7}, {%8,%9}, {%0,%1,%2,%3};"
                 : "+f"(d[0]), "+f"(d[1]), "+f"(d[2]), "+f"(d[3])
                 : "r"(a[0]), "r"(a[1]), "r"(a[2]), "r"(a[3]), "r"(bb[0]), "r"(bb[1]));
}

__global__ __launch_bounds__(512, 1) void k_conv(float* __restrict__ y) {
    extern __shared__ __align__(128) unsigned char smem[];
    const unsigned sb = (unsigned)__cvta_generic_to_shared(smem);
    // mbarriers: full0 @+0, full1 @+8 (tx, 1 arrival); empty0 @+16, empty1 @+24 (512 arrivals)

    const int tid = threadIdx.x;
    const int ln  = tid & 31;
    const int w   = tid >> 5;
    const int g   = ln >> 2;
    const int tig = ln & 3;
    const int wr  = w >> 1;              // output row within tile (0..7)
    const int cw  = (w & 1) * 32;        // column half

    const int h0  = blockIdx.x * 8;
    const int coh = blockIdx.y;
    const int b   = blockIdx.z;

    const unsigned aLane = ((unsigned)((ln >> 4)*64 + (ln & 15)))*400u;

    if (tid == 0) {
        asm volatile("mbarrier.init.shared.b64 [%0], 1;"   :: "r"(sb+0)  : "memory");
        asm volatile("mbarrier.init.shared.b64 [%0], 1;"   :: "r"(sb+8)  : "memory");
        asm volatile("mbarrier.init.shared.b64 [%0], 512;" :: "r"(sb+16) : "memory");
        asm volatile("mbarrier.init.shared.b64 [%0], 512;" :: "r"(sb+24) : "memory");
    }
    __syncthreads();

    auto stage = [&](int cs, int bufi) {
        unsigned mb = sb + bufi*8;
        asm volatile("mbarrier.arrive.expect_tx.shared.b64 _, [%0], %1;"
                     :: "r"(mb), "r"((unsigned)TX_BYTES) : "memory");
        bulk(sb + WS0_OFF + bufi*WS_BYTES,
             g_lphB + ((size_t)(b*8 + cs)*2 + coh)*25600, WS_BYTES, mb);
        #pragma unroll
        for (int pl = 0; pl < 8; pl++)
            bulk(sb + XS0_OFF + bufi*XS_BYTES + pl*(XS_PLANE*4),
                 g_xh + ((size_t)(b*64 + cs*8 + pl)*68 + h0)*72,
                 3456, mb);
    };

    float acc[4][4][4];
    #pragma unroll
    for (int mf = 0; mf < 4; mf++)
        #pragma unroll
        for (int f = 0; f < 4; f++)
            #pragma unroll
            for (int r = 0; r < 4; r++) acc[mf][f][r] = 0.f;

    if (tid == 0) { stage(0, 0); stage(1, 1); }

    #pragma unroll 1
    for (int cc = 0; cc < 8; cc++) {
        const int bufi = cc & 1;
        // full[bufi] completes at cc = bufi, bufi+2, ... -> phase cc>>1
        mbwait(sb + bufi*8, (cc >> 1) & 1);

        const unsigned  aBase = sb + WS0_OFF + bufi*WS_BYTES + aLane;
        const unsigned* XS    = (const unsigned*)(smem + XS0_OFF + bufi*XS_BYTES);
        const int xbase = wr*72 + 2 + cw + g;

        #pragma unroll
        for (int dh = 0; dh < 5; dh++) {
            #pragma unroll
            for (int dw = 0; dw < 5; dw++) {
                const int tap = dh*5 + dw;
                unsigned a[4][4];
                #pragma unroll
                for (int mf = 0; mf < 4; mf++)
                    ldsm4(a[mf], aBase + mf*6400 + tap*16);

                unsigned bb[4][2];
                const int xo = xbase + dh*72 + dw;
                #pragma unroll
                for (int f = 0; f < 4; f++) {
                    bb[f][0] = XS[tig*XS_PLANE       + xo + 8*f];
                    bb[f][1] = XS[(tig + 4)*XS_PLANE + xo + 8*f];
                }
                #pragma unroll
                for (int mf = 0; mf < 4; mf++)
                    #pragma unroll
                    for (int f = 0; f < 4; f++)
                        mma16(acc[mf][f], a[mf], bb[f]);
            }
        }

        // signal this buffer consumed; only thread 0 blocks to restage it
        mbarrive(sb + 16 + bufi*8);
        if (cc < 6 && tid == 0) {
            // empty[bufi] completes at cc = bufi, bufi+2, ... -> phase cc>>1
            mbwait(sb + 16 + bufi*8, (cc >> 1) & 1);
            stage(cc + 2, bufi);
        }
    }

    // epilogue
    const int hw = h0 + wr;
    #pragma unroll
    for (int mf = 0; mf < 4; mf++) {
        #pragma unroll
        for (int f = 0; f < 4; f++) {
            int co = coh*64 + 16*mf + g;
            int px = cw + 8*f + 2*tig;
            float* yp = y + (((size_t)b*CO_ + co)*H_ + hw)*W_ + px;
            *(float2*)yp             = make_float2(acc[mf][f][0], acc[mf][f][1]);
            *(float2*)(yp + 8*H_*W_) = make_float2(acc[mf][f][2], acc[mf][f][3]);
        }
    }
}

// ---------------------------------------------------------------------------
// Launch
// ---------------------------------------------------------------------------
extern "C" void kernel_launch(void* const* d_in, const int* in_sizes, int n_in,
                              void* d_out, int out_size) {
    const float* x  = (const float*)d_in[0];
    const float* tf = (const float*)d_in[1];
    const float* Wb = (const float*)d_in[2];
    float* y        = (float*)d_out;

    cudaFuncSetAttribute(k_conv, cudaFuncAttributeMaxDynamicSharedMemorySize, SMEM_BYTES);

    k_prep<<<NWB + NXB, 256>>>(x, tf, Wb);
    dim3 grid(8, 2, B_);
    k_conv<<<grid, 512, SMEM_BYTES>>>(y);
    (void)in_sizes; (void)n_in; (void)out_size;
}

// round 15
// speedup vs baseline: 1.3052x; 1.0093x over previous
#include <cuda_runtime.h>
#include <cuda_fp16.h>
#include <cstdint>
#include <cstddef>

#define B_   16
#define T_   8
#define KB_  64
#define CO_  128
#define CI_  128
#define H_   64
#define W_   64
#define WELEMS (CO_*CI_*25)

// ---------------------------------------------------------------------------
// Scratch (__device__ globals; zero-initialized, allocation-free rule)
// ---------------------------------------------------------------------------
// padded half2 x planes: [b][pl64][row68][word72]; image row h -> row h+2,
// px p -> word p+4. Halo rows/cols stay zero (never written).
__device__ __align__(16) unsigned g_xh[(size_t)B_*64*68*72];
// weights: [b][chunk8][coh2] contiguous 51200B blocks: [kk2][co64][tap25][ci8]
__device__ __align__(16) __half g_lphB[(size_t)B_*8*2*25600];

// ---------------------------------------------------------------------------
// packed f32x2 helpers (Blackwell FFMA2 path)
// ---------------------------------------------------------------------------
__device__ __forceinline__ unsigned long long ffma2(unsigned long long a,
                                                    unsigned long long b,
                                                    unsigned long long c) {
    unsigned long long d;
    asm("fma.rn.f32x2 %0, %1, %2, %3;" : "=l"(d) : "l"(a), "l"(b), "l"(c));
    return d;
}
__device__ __forceinline__ unsigned long long packdup(float v) {
    unsigned long long o; unsigned u = __float_as_uint(v);
    asm("mov.b64 %0, {%1, %2};" : "=l"(o) : "r"(u), "r"(u));
    return o;
}
__device__ __forceinline__ void unpack2(float& lo, float& hi, unsigned long long v) {
    unsigned a, b;
    asm("mov.b64 {%0, %1}, %2;" : "=r"(a), "=r"(b) : "l"(v));
    lo = __uint_as_float(a); hi = __uint_as_float(b);
}

// ---------------------------------------------------------------------------
// Kernel P: fused prep (wsum blocks + xcvt blocks, concurrent).
// ---------------------------------------------------------------------------
#define NWB 512
#define NXB 512

__global__ __launch_bounds__(256) void k_prep(const float* __restrict__ x,
                                              const float* __restrict__ tf,
                                              const float* __restrict__ Wb) {
    const int blk = blockIdx.x;
    const int tid = threadIdx.x;

    if (blk < NWB) {
        // ---------------- wsum (FFMA2, batched-MLP k loop) ----------------
        __shared__ __align__(8)  float sst[64][16];   // [k][b] transposed
        __shared__ __align__(16) float wbuf[2][800];

        for (int i = tid; i < B_*KB_; i += 256) {
            int b = i >> 6, k = i & 63;
            float a = 0.f;
            #pragma unroll
            for (int t = 0; t < T_; t++) a += tf[(b*T_ + t)*KB_ + k];
            sst[k][b] = a * (1.0f / T_);
        }
        __syncthreads();

        const int co = blk >> 2;
        const int q  = blk & 3;               // ci quarter (32 ci)
        const bool act = tid < 200;
        const float* src = Wb + co*3200 + q*800 + 4*tid;

        unsigned long long accp[8][4];        // [b-pair][component]
        #pragma unroll
        for (int i = 0; i < 8; i++)
            #pragma unroll
            for (int c = 0; c < 4; c++) accp[i][c] = 0ull;

        if (act) {
            #pragma unroll 1
            for (int k0 = 0; k0 < KB_; k0 += 8) {
                float4 wv[8];                 // 8 front-batched LDG.128 (MLP=8)
                #pragma unroll
                for (int j = 0; j < 8; j++)
                    wv[j] = *(const float4*)(src + (size_t)(k0 + j)*WELEMS);
                #pragma unroll
                for (int j = 0; j < 8; j++) {
                    unsigned long long wx = packdup(wv[j].x), wy = packdup(wv[j].y);
                    unsigned long long wz = packdup(wv[j].z), ww = packdup(wv[j].w);
                    const unsigned long long* sp =
                        (const unsigned long long*)&sst[k0 + j][0];
                    #pragma unroll
                    for (int i = 0; i < 8; i++) {
                        unsigned long long s2 = sp[i];
                        accp[i][0] = ffma2(s2, wx, accp[i][0]);
                        accp[i][1] = ffma2(s2, wy, accp[i][1]);
                        accp[i][2] = ffma2(s2, wz, accp[i][2]);
                        accp[i][3] = ffma2(s2, ww, accp[i][3]);
                    }
                }
            }
        }

        const int bsel  = tid / 100;
        const int t2    = tid % 100;
        const int tap   = t2 % 25;
        const int c8    = t2 / 25;            // ci8-block within quarter
        const int chunk = 2*q + (c8 >> 1);
        const int kk    = c8 & 1;
        const int coh   = co >> 6;
        const int c64   = co & 63;
        #pragma unroll 1
        for (int bp = 0; bp < 8; bp++) {
            if (act) {
                float4 a0, a1;
                unpack2(a0.x, a1.x, accp[bp][0]);
                unpack2(a0.y, a1.y, accp[bp][1]);
                unpack2(a0.z, a1.z, accp[bp][2]);
                unpack2(a0.w, a1.w, accp[bp][3]);
                *(float4*)(wbuf[0] + 4*tid) = a0;
                *(float4*)(wbuf[1] + 4*tid) = a1;
            }
            __syncthreads();
            if (tid < 200) {
                __half h[8];
                #pragma unroll
                for (int i2 = 0; i2 < 8; i2++)
                    h[i2] = __float2half_rn(wbuf[bsel][(c8*8 + i2)*25 + tap]);
                int b = 2*bp + bsel;
                size_t o = (((size_t)(b*8 + chunk)*2 + coh)*25600)
                         + (((size_t)kk*64 + c64)*25 + tap)*8;
                *(uint4*)(g_lphB + o) = *(const uint4*)h;
            }
            __syncthreads();
        }
    } else {
        // ---------------- xcvt: write padded planes (interior only) --------
        const size_t total4 = (size_t)B_*64*H_*W_ / 4;
        for (size_t e = (size_t)(blk - NWB)*256 + tid; e < total4;
             e += (size_t)NXB*256) {
            size_t i = e * 4;
            int px   = (int)(i & 63);
            int rest = (int)(i >> 6);
            int h    = rest & 63;
            int pr   = rest >> 6;
            int pl   = pr & 63;
            int b    = pr >> 6;
            const float* xb = x + ((size_t)(b*CI_ + 2*pl)*H_ + h)*W_ + px;
            float4 lo = *(const float4*)xb;
            float4 hi = *(const float4*)(xb + H_*W_);
            uint4 o;
            __half2 p0 = __floats2half2_rn(lo.x, hi.x);
            __half2 p1 = __floats2half2_rn(lo.y, hi.y);
            __half2 p2 = __floats2half2_rn(lo.z, hi.z);
            __half2 p3 = __floats2half2_rn(lo.w, hi.w);
            o.x = *(unsigned*)&p0; o.y = *(unsigned*)&p1;
            o.z = *(unsigned*)&p2; o.w = *(unsigned*)&p3;
            size_t dst = ((size_t)(b*64 + pl)*68 + h + 2)*72 + px + 4;
            *(uint4*)(g_xh + dst) = o;
        }
    }
}

// ---------------------------------------------------------------------------
// Kernel C: fp16 m16n8k16 conv, double-buffered cp.async.bulk pipeline with
// full/empty mbarriers. 512 thr, 1 CTA/SM. Tile 64co x (8 rows x 64 px).
// (unchanged from round 13 — proven at 127 us)
// ---------------------------------------------------------------------------
#define WS0_OFF   1024
#define WS_BYTES  51200
#define XS0_OFF   (WS0_OFF + 2*WS_BYTES)          // 103424
#define XS_PLANE  872                             // words per plane (12*72 + 8)
#define XS_BYTES  (8*XS_PLANE*4)                  // 27904
#define SMEM_BYTES (XS0_OFF + 2*XS_BYTES)         // 159232
#define TX_BYTES  (WS_BYTES + 8*3456)             // 78848

__device__ __forceinline__ void bulk(unsigned dst, const void* src, unsigned n, unsigned mb) {
    asm volatile("cp.async.bulk.shared::cta.global.mbarrier::complete_tx::bytes [%0], [%1], %2, [%3];"
                 :: "r"(dst), "l"(src), "r"(n), "r"(mb) : "memory");
}
__device__ __forceinline__ void mbwait(unsigned mb, unsigned par) {
    asm volatile("{\n\t.reg .pred P;\n\tWL%=:\n\t"
                 "mbarrier.try_wait.parity.acquire.cta.shared::cta.b64 P, [%0], %1, 0x989680;\n\t"
                 "@P bra.uni WD%=;\n\tbra.uni WL%=;\n\tWD%=:\n\t}"
                 :: "r"(mb), "r"(par) : "memory");
}
__device__ __forceinline__ void mbarrive(unsigned mb) {
    asm volatile("mbarrier.arrive.shared.b64 _, [%0];" :: "r"(mb) : "memory");
}
__device__ __forceinline__ void ldsm4(unsigned* r, unsigned addr) {
    asm volatile("ldmatrix.sync.aligned.m8n8.x4.shared.b16 {%0,%1,%2,%3}, [%4];"
                 : "=r"(r[0]), "=r"(r[1]), "=r"(r[2]), "=r"(r[3]) : "r"(addr));
}
__device__ __forceinline__ void mma16(float* d, const unsigned* a, const unsigned* bb) {
    asm volatile("mma.sync.aligned.m16n8k16.row.col.f32.f16.f16.f32 "
                 "{%0,%1,%2,%3}, {%4,%5,%6,%7}, {%8,%9}, {%0,%1,%2,%3};"
                 : "+f"(d[0]), "+f"(d[1]), "+f"(d[2]), "+f"(d[3])
                 : "r"(a[0]), "r"(a[1]), "r"(a[2]), "r"(a[3]), "r"(bb[0]), "r"(bb[1]));
}

__global__ __launch_bounds__(512, 1) void k_conv(float* __restrict__ y) {
    extern __shared__ __align__(128) unsigned char smem[];
    const unsigned sb = (unsigned)__cvta_generic_to_shared(smem);

    const int tid = threadIdx.x;
    const int ln  = tid & 31;
    const int w   = tid >> 5;
    const int g   = ln >> 2;
    const int tig = ln & 3;
    const int wr  = w >> 1;
    const int cw  = (w & 1) * 32;

    const int h0  = blockIdx.x * 8;
    const int coh = blockIdx.y;
    const int b   = blockIdx.z;

    const unsigned aLane = ((unsigned)((ln >> 4)*64 + (ln & 15)))*400u;

    if (tid == 0) {
        asm volatile("mbarrier.init.shared.b64 [%0], 1;"   :: "r"(sb+0)  : "memory");
        asm volatile("mbarrier.init.shared.b64 [%0], 1;"   :: "r"(sb+8)  : "memory");
        asm volatile("mbarrier.init.shared.b64 [%0], 512;" :: "r"(sb+16) : "memory");
        asm volatile("mbarrier.init.shared.b64 [%0], 512;" :: "r"(sb+24) : "memory");
    }
    __syncthreads();

    auto stage = [&](int cs, int bufi) {
        unsigned mb = sb + bufi*8;
        asm volatile("mbarrier.arrive.expect_tx.shared.b64 _, [%0], %1;"
                     :: "r"(mb), "r"((unsigned)TX_BYTES) : "memory");
        bulk(sb + WS0_OFF + bufi*WS_BYTES,
             g_lphB + ((size_t)(b*8 + cs)*2 + coh)*25600, WS_BYTES, mb);
        #pragma unroll
        for (int pl = 0; pl < 8; pl++)
            bulk(sb + XS0_OFF + bufi*XS_BYTES + pl*(XS_PLANE*4),
                 g_xh + ((size_t)(b*64 + cs*8 + pl)*68 + h0)*72,
                 3456, mb);
    };

    float acc[4][4][4];
    #pragma unroll
    for (int mf = 0; mf < 4; mf++)
        #pragma unroll
        for (int f = 0; f < 4; f++)
            #pragma unroll
            for (int r = 0; r < 4; r++) acc[mf][f][r] = 0.f;

    if (tid == 0) { stage(0, 0); stage(1, 1); }

    #pragma unroll 1
    for (int cc = 0; cc < 8; cc++) {
        const int bufi = cc & 1;
        mbwait(sb + bufi*8, (cc >> 1) & 1);

        const unsigned  aBase = sb + WS0_OFF + bufi*WS_BYTES + aLane;
        const unsigned* XS    = (const unsigned*)(smem + XS0_OFF + bufi*XS_BYTES);
        const int xbase = wr*72 + 2 + cw + g;

        #pragma unroll
        for (int dh = 0; dh < 5; dh++) {
            #pragma unroll
            for (int dw = 0; dw < 5; dw++) {
                const int tap = dh*5 + dw;
                unsigned a[4][4];
                #pragma unroll
                for (int mf = 0; mf < 4; mf++)
                    ldsm4(a[mf], aBase + mf*6400 + tap*16);

                unsigned bb[4][2];
                const int xo = xbase + dh*72 + dw;
                #pragma unroll
                for (int f = 0; f < 4; f++) {
                    bb[f][0] = XS[tig*XS_PLANE       + xo + 8*f];
                    bb[f][1] = XS[(tig + 4)*XS_PLANE + xo + 8*f];
                }
                #pragma unroll
                for (int mf = 0; mf < 4; mf++)
                    #pragma unroll
                    for (int f = 0; f < 4; f++)
                        mma16(acc[mf][f], a[mf], bb[f]);
            }
        }

        mbarrive(sb + 16 + bufi*8);
        if (cc < 6 && tid == 0) {
            mbwait(sb + 16 + bufi*8, (cc >> 1) & 1);
            stage(cc + 2, bufi);
        }
    }

    const int hw = h0 + wr;
    #pragma unroll
    for (int mf = 0; mf < 4; mf++) {
        #pragma unroll
        for (int f = 0; f < 4; f++) {
            int co = coh*64 + 16*mf + g;
            int px = cw + 8*f + 2*tig;
            float* yp = y + (((size_t)b*CO_ + co)*H_ + hw)*W_ + px;
            *(float2*)yp             = make_float2(acc[mf][f][0], acc[mf][f][1]);
            *(float2*)(yp + 8*H_*W_) = make_float2(acc[mf][f][2], acc[mf][f][3]);
        }
    }
}

// ---------------------------------------------------------------------------
// Launch
// ---------------------------------------------------------------------------
extern "C" void kernel_launch(void* const* d_in, const int* in_sizes, int n_in,
                              void* d_out, int out_size) {
    const float* x  = (const float*)d_in[0];
    const float* tf = (const float*)d_in[1];
    const float* Wb = (const float*)d_in[2];
    float* y        = (float*)d_out;

    cudaFuncSetAttribute(k_conv, cudaFuncAttributeMaxDynamicSharedMemorySize, SMEM_BYTES);

    k_prep<<<NWB + NXB, 256>>>(x, tf, Wb);
    dim3 grid(8, 2, B_);
    k_conv<<<grid, 512, SMEM_BYTES>>>(y);
    (void)in_sizes; (void)n_in; (void)out_size;
}

// round 16
// speedup vs baseline: 1.3677x; 1.0479x over previous
#include <cuda_runtime.h>
#include <cuda_fp16.h>
#include <cstdint>
#include <cstddef>

#define B_   16
#define T_   8
#define KB_  64
#define CO_  128
#define CI_  128
#define H_   64
#define W_   64
#define WELEMS (CO_*CI_*25)

// ---------------------------------------------------------------------------
// Scratch (__device__ globals; zero-initialized, allocation-free rule)
// ---------------------------------------------------------------------------
// padded half2 x planes: [b][pl64][row68][word72]; image row h -> row h+2,
// px p -> word p+4. Halo rows/cols stay zero (never written).
__device__ __align__(16) unsigned g_xh[(size_t)B_*64*68*72];
// weights: [b][chunk8][coh2] contiguous 51200B blocks: [kk2][co64][tap25][ci8]
__device__ __align__(16) __half g_lphB[(size_t)B_*8*2*25600];

// ---------------------------------------------------------------------------
// packed f32x2 helpers (Blackwell FFMA2 path)
// ---------------------------------------------------------------------------
__device__ __forceinline__ unsigned long long ffma2(unsigned long long a,
                                                    unsigned long long b,
                                                    unsigned long long c) {
    unsigned long long d;
    asm("fma.rn.f32x2 %0, %1, %2, %3;" : "=l"(d) : "l"(a), "l"(b), "l"(c));
    return d;
}
__device__ __forceinline__ unsigned long long packdup(float v) {
    unsigned long long o; unsigned u = __float_as_uint(v);
    asm("mov.b64 %0, {%1, %2};" : "=l"(o) : "r"(u), "r"(u));
    return o;
}
__device__ __forceinline__ void unpack2(float& lo, float& hi, unsigned long long v) {
    unsigned a, b;
    asm("mov.b64 {%0, %1}, %2;" : "=r"(a), "=r"(b) : "l"(v));
    lo = __uint_as_float(a); hi = __uint_as_float(b);
}

// ---------------------------------------------------------------------------
// Kernel P: fused prep (wsum blocks + xcvt blocks, concurrent).
// __launch_bounds__(256, 2): cap 128 regs -> 2 blocks/SM (occupancy was the
// limiter: accp(64) + wv batch pushed regs past 128 -> 1 block/SM, 7 waves).
// Load batch reduced to 4 so the cap doesn't spill.
// ---------------------------------------------------------------------------
#define NWB 512
#define NXB 512

__global__ __launch_bounds__(256, 2) void k_prep(const float* __restrict__ x,
                                                 const float* __restrict__ tf,
                                                 const float* __restrict__ Wb) {
    const int blk = blockIdx.x;
    const int tid = threadIdx.x;

    if (blk < NWB) {
        // ---------------- wsum (FFMA2, batch-4 k loop) ----------------
        __shared__ __align__(8)  float sst[64][16];   // [k][b] transposed
        __shared__ __align__(16) float wbuf[2][800];

        for (int i = tid; i < B_*KB_; i += 256) {
            int b = i >> 6, k = i & 63;
            float a = 0.f;
            #pragma unroll
            for (int t = 0; t < T_; t++) a += tf[(b*T_ + t)*KB_ + k];
            sst[k][b] = a * (1.0f / T_);
        }
        __syncthreads();

        const int co = blk >> 2;
        const int q  = blk & 3;               // ci quarter (32 ci)
        const bool act = tid < 200;
        const float* src = Wb + co*3200 + q*800 + 4*tid;

        unsigned long long accp[8][4];        // [b-pair][component]
        #pragma unroll
        for (int i = 0; i < 8; i++)
            #pragma unroll
            for (int c = 0; c < 4; c++) accp[i][c] = 0ull;

        if (act) {
            #pragma unroll 1
            for (int k0 = 0; k0 < KB_; k0 += 4) {
                float4 wv[4];                 // 4 front-batched LDG.128
                #pragma unroll
                for (int j = 0; j < 4; j++)
                    wv[j] = *(const float4*)(src + (size_t)(k0 + j)*WELEMS);
                #pragma unroll
                for (int j = 0; j < 4; j++) {
                    unsigned long long wx = packdup(wv[j].x), wy = packdup(wv[j].y);
                    unsigned long long wz = packdup(wv[j].z), ww = packdup(wv[j].w);
                    const unsigned long long* sp =
                        (const unsigned long long*)&sst[k0 + j][0];
                    #pragma unroll
                    for (int i = 0; i < 8; i++) {
                        unsigned long long s2 = sp[i];
                        accp[i][0] = ffma2(s2, wx, accp[i][0]);
                        accp[i][1] = ffma2(s2, wy, accp[i][1]);
                        accp[i][2] = ffma2(s2, wz, accp[i][2]);
                        accp[i][3] = ffma2(s2, ww, accp[i][3]);
                    }
                }
            }
        }

        const int bsel  = tid / 100;
        const int t2    = tid % 100;
        const int tap   = t2 % 25;
        const int c8    = t2 / 25;            // ci8-block within quarter
        const int chunk = 2*q + (c8 >> 1);
        const int kk    = c8 & 1;
        const int coh   = co >> 6;
        const int c64   = co & 63;
        #pragma unroll 1
        for (int bp = 0; bp < 8; bp++) {
            if (act) {
                float4 a0, a1;
                unpack2(a0.x, a1.x, accp[bp][0]);
                unpack2(a0.y, a1.y, accp[bp][1]);
                unpack2(a0.z, a1.z, accp[bp][2]);
                unpack2(a0.w, a1.w, accp[bp][3]);
                *(float4*)(wbuf[0] + 4*tid) = a0;
                *(float4*)(wbuf[1] + 4*tid) = a1;
            }
            __syncthreads();
            if (tid < 200) {
                __half h[8];
                #pragma unroll
                for (int i2 = 0; i2 < 8; i2++)
                    h[i2] = __float2half_rn(wbuf[bsel][(c8*8 + i2)*25 + tap]);
                int b = 2*bp + bsel;
                size_t o = (((size_t)(b*8 + chunk)*2 + coh)*25600)
                         + (((size_t)kk*64 + c64)*25 + tap)*8;
                *(uint4*)(g_lphB + o) = *(const uint4*)h;
            }
            __syncthreads();
        }
    } else {
        // ---------------- xcvt: write padded planes (interior only) --------
        const size_t total4 = (size_t)B_*64*H_*W_ / 4;
        for (size_t e = (size_t)(blk - NWB)*256 + tid; e < total4;
             e += (size_t)NXB*256) {
            size_t i = e * 4;
            int px   = (int)(i & 63);
            int rest = (int)(i >> 6);
            int h    = rest & 63;
            int pr   = rest >> 6;
            int pl   = pr & 63;
            int b    = pr >> 6;
            const float* xb = x + ((size_t)(b*CI_ + 2*pl)*H_ + h)*W_ + px;
            float4 lo = *(const float4*)xb;
            float4 hi = *(const float4*)(xb + H_*W_);
            uint4 o;
            __half2 p0 = __floats2half2_rn(lo.x, hi.x);
            __half2 p1 = __floats2half2_rn(lo.y, hi.y);
            __half2 p2 = __floats2half2_rn(lo.z, hi.z);
            __half2 p3 = __floats2half2_rn(lo.w, hi.w);
            o.x = *(unsigned*)&p0; o.y = *(unsigned*)&p1;
            o.z = *(unsigned*)&p2; o.w = *(unsigned*)&p3;
            size_t dst = ((size_t)(b*64 + pl)*68 + h + 2)*72 + px + 4;
            *(uint4*)(g_xh + dst) = o;
        }
    }
}

// ---------------------------------------------------------------------------
// Kernel C: fp16 m16n8k16 conv, double-buffered cp.async.bulk pipeline with
// full/empty mbarriers. 512 thr, 1 CTA/SM. Tile 64co x (8 rows x 64 px).
// (unchanged — proven at 126 us)
// ---------------------------------------------------------------------------
#define WS0_OFF   1024
#define WS_BYTES  51200
#define XS0_OFF   (WS0_OFF + 2*WS_BYTES)          // 103424
#define XS_PLANE  872                             // words per plane (12*72 + 8)
#define XS_BYTES  (8*XS_PLANE*4)                  // 27904
#define SMEM_BYTES (XS0_OFF + 2*XS_BYTES)         // 159232
#define TX_BYTES  (WS_BYTES + 8*3456)             // 78848

__device__ __forceinline__ void bulk(unsigned dst, const void* src, unsigned n, unsigned mb) {
    asm volatile("cp.async.bulk.shared::cta.global.mbarrier::complete_tx::bytes [%0], [%1], %2, [%3];"
                 :: "r"(dst), "l"(src), "r"(n), "r"(mb) : "memory");
}
__device__ __forceinline__ void mbwait(unsigned mb, unsigned par) {
    asm volatile("{\n\t.reg .pred P;\n\tWL%=:\n\t"
                 "mbarrier.try_wait.parity.acquire.cta.shared::cta.b64 P, [%0], %1, 0x989680;\n\t"
                 "@P bra.uni WD%=;\n\tbra.uni WL%=;\n\tWD%=:\n\t}"
                 :: "r"(mb), "r"(par) : "memory");
}
__device__ __forceinline__ void mbarrive(unsigned mb) {
    asm volatile("mbarrier.arrive.shared.b64 _, [%0];" :: "r"(mb) : "memory");
}
__device__ __forceinline__ void ldsm4(unsigned* r, unsigned addr) {
    asm volatile("ldmatrix.sync.aligned.m8n8.x4.shared.b16 {%0,%1,%2,%3}, [%4];"
                 : "=r"(r[0]), "=r"(r[1]), "=r"(r[2]), "=r"(r[3]) : "r"(addr));
}
__device__ __forceinline__ void mma16(float* d, const unsigned* a, const unsigned* bb) {
    asm volatile("mma.sync.aligned.m16n8k16.row.col.f32.f16.f16.f32 "
                 "{%0,%1,%2,%3}, {%4,%5,%6,%7}, {%8,%9}, {%0,%1,%2,%3};"
                 : "+f"(d[0]), "+f"(d[1]), "+f"(d[2]), "+f"(d[3])
                 : "r"(a[0]), "r"(a[1]), "r"(a[2]), "r"(a[3]), "r"(bb[0]), "r"(bb[1]));
}

__global__ __launch_bounds__(512, 1) void k_conv(float* __restrict__ y) {
    extern __shared__ __align__(128) unsigned char smem[];
    const unsigned sb = (unsigned)__cvta_generic_to_shared(smem);

    const int tid = threadIdx.x;
    const int ln  = tid & 31;
    const int w   = tid >> 5;
    const int g   = ln >> 2;
    const int tig = ln & 3;
    const int wr  = w >> 1;
    const int cw  = (w & 1) * 32;

    const int h0  = blockIdx.x * 8;
    const int coh = blockIdx.y;
    const int b   = blockIdx.z;

    const unsigned aLane = ((unsigned)((ln >> 4)*64 + (ln & 15)))*400u;

    if (tid == 0) {
        asm volatile("mbarrier.init.shared.b64 [%0], 1;"   :: "r"(sb+0)  : "memory");
        asm volatile("mbarrier.init.shared.b64 [%0], 1;"   :: "r"(sb+8)  : "memory");
        asm volatile("mbarrier.init.shared.b64 [%0], 512;" :: "r"(sb+16) : "memory");
        asm volatile("mbarrier.init.shared.b64 [%0], 512;" :: "r"(sb+24) : "memory");
    }
    __syncthreads();

    auto stage = [&](int cs, int bufi) {
        unsigned mb = sb + bufi*8;
        asm volatile("mbarrier.arrive.expect_tx.shared.b64 _, [%0], %1;"
                     :: "r"(mb), "r"((unsigned)TX_BYTES) : "memory");
        bulk(sb + WS0_OFF + bufi*WS_BYTES,
             g_lphB + ((size_t)(b*8 + cs)*2 + coh)*25600, WS_BYTES, mb);
        #pragma unroll
        for (int pl = 0; pl < 8; pl++)
            bulk(sb + XS0_OFF + bufi*XS_BYTES + pl*(XS_PLANE*4),
                 g_xh + ((size_t)(b*64 + cs*8 + pl)*68 + h0)*72,
                 3456, mb);
    };

    float acc[4][4][4];
    #pragma unroll
    for (int mf = 0; mf < 4; mf++)
        #pragma unroll
        for (int f = 0; f < 4; f++)
            #pragma unroll
            for (int r = 0; r < 4; r++) acc[mf][f][r] = 0.f;

    if (tid == 0) { stage(0, 0); stage(1, 1); }

    #pragma unroll 1
    for (int cc = 0; cc < 8; cc++) {
        const int bufi = cc & 1;
        mbwait(sb + bufi*8, (cc >> 1) & 1);

        const unsigned  aBase = sb + WS0_OFF + bufi*WS_BYTES + aLane;
        const unsigned* XS    = (const unsigned*)(smem + XS0_OFF + bufi*XS_BYTES);
        const int xbase = wr*72 + 2 + cw + g;

        #pragma unroll
        for (int dh = 0; dh < 5; dh++) {
            #pragma unroll
            for (int dw = 0; dw < 5; dw++) {
                const int tap = dh*5 + dw;
                unsigned a[4][4];
                #pragma unroll
                for (int mf = 0; mf < 4; mf++)
                    ldsm4(a[mf], aBase + mf*6400 + tap*16);

                unsigned bb[4][2];
                const int xo = xbase + dh*72 + dw;
                #pragma unroll
                for (int f = 0; f < 4; f++) {
                    bb[f][0] = XS[tig*XS_PLANE       + xo + 8*f];
                    bb[f][1] = XS[(tig + 4)*XS_PLANE + xo + 8*f];
                }
                #pragma unroll
                for (int mf = 0; mf < 4; mf++)
                    #pragma unroll
                    for (int f = 0; f < 4; f++)
                        mma16(acc[mf][f], a[mf], bb[f]);
            }
        }

        mbarrive(sb + 16 + bufi*8);
        if (cc < 6 && tid == 0) {
            mbwait(sb + 16 + bufi*8, (cc >> 1) & 1);
            stage(cc + 2, bufi);
        }
    }

    const int hw = h0 + wr;
    #pragma unroll
    for (int mf = 0; mf < 4; mf++) {
        #pragma unroll
        for (int f = 0; f < 4; f++) {
            int co = coh*64 + 16*mf + g;
            int px = cw + 8*f + 2*tig;
            float* yp = y + (((size_t)b*CO_ + co)*H_ + hw)*W_ + px;
            *(float2*)yp             = make_float2(acc[mf][f][0], acc[mf][f][1]);
            *(float2*)(yp + 8*H_*W_) = make_float2(acc[mf][f][2], acc[mf][f][3]);
        }
    }
}

// ---------------------------------------------------------------------------
// Launch
// ---------------------------------------------------------------------------
extern "C" void kernel_launch(void* const* d_in, const int* in_sizes, int n_in,
                              void* d_out, int out_size) {
    const float* x  = (const float*)d_in[0];
    const float* tf = (const float*)d_in[1];
    const float* Wb = (const float*)d_in[2];
    float* y        = (float*)d_out;

    cudaFuncSetAttribute(k_conv, cudaFuncAttributeMaxDynamicSharedMemorySize, SMEM_BYTES);

    k_prep<<<NWB + NXB, 256>>>(x, tf, Wb);
    dim3 grid(8, 2, B_);
    k_conv<<<grid, 512, SMEM_BYTES>>>(y);
    (void)in_sizes; (void)n_in; (void)out_size;
}

// round 17
// speedup vs baseline: 1.3849x; 1.0126x over previous
#include <cuda_runtime.h>
#include <cuda_fp16.h>
#include <cstdint>
#include <cstddef>

#define B_   16
#define T_   8
#define KB_  64
#define CO_  128
#define CI_  128
#define H_   64
#define W_   64
#define WELEMS (CO_*CI_*25)

// ---------------------------------------------------------------------------
// Scratch (__device__ globals; zero-initialized, allocation-free rule)
// ---------------------------------------------------------------------------
// padded half2 x planes: [b][pl64][row68][word72]; image row h -> row h+2,
// px p -> word p+4. Halo rows/cols stay zero (never written).
__device__ __align__(16) unsigned g_xh[(size_t)B_*64*68*72];
// weights: [b][chunk8][coh2] contiguous 51200B blocks: [kk2][co64][tap25][ci8]
__device__ __align__(16) __half g_lphB[(size_t)B_*8*2*25600];

// ---------------------------------------------------------------------------
// packed f32x2 helpers (Blackwell FFMA2 path)
// ---------------------------------------------------------------------------
__device__ __forceinline__ unsigned long long ffma2(unsigned long long a,
                                                    unsigned long long b,
                                                    unsigned long long c) {
    unsigned long long d;
    asm("fma.rn.f32x2 %0, %1, %2, %3;" : "=l"(d) : "l"(a), "l"(b), "l"(c));
    return d;
}
__device__ __forceinline__ unsigned long long packdup(float v) {
    unsigned long long o; unsigned u = __float_as_uint(v);
    asm("mov.b64 %0, {%1, %2};" : "=l"(o) : "r"(u), "r"(u));
    return o;
}
__device__ __forceinline__ void unpack2(float& lo, float& hi, unsigned long long v) {
    unsigned a, b;
    asm("mov.b64 {%0, %1}, %2;" : "=r"(a), "=r"(b) : "l"(v));
    lo = __uint_as_float(a); hi = __uint_as_float(b);
}

// ---------------------------------------------------------------------------
// Kernel P: fused prep. 592 blocks = EXACTLY 2 waves at 2 blocks/SM.
// Every 8th block (blk%8==7) is an xcvt block (74 total, grid-stride);
// the rest are wsum blocks (518 slots, first 512 active). Interleaving puts
// DRAM-heavy xcvt alongside compute-heavy wsum in BOTH waves.
// ---------------------------------------------------------------------------
#define NPREP 592
#define NXB   74

__global__ __launch_bounds__(256, 2) void k_prep(const float* __restrict__ x,
                                                 const float* __restrict__ tf,
                                                 const float* __restrict__ Wb) {
    const int blk = blockIdx.x;
    const int tid = threadIdx.x;

    if ((blk & 7) != 7) {
        // ---------------- wsum (FFMA2, batch-4 k loop) ----------------
        const int wi = blk - (blk >> 3);      // wsum index (xcvt blocks removed)
        if (wi >= 512) return;

        __shared__ __align__(8)  float sst[64][16];   // [k][b] transposed
        __shared__ __align__(16) float wbuf[2][800];

        for (int i = tid; i < B_*KB_; i += 256) {
            int b = i >> 6, k = i & 63;
            float a = 0.f;
            #pragma unroll
            for (int t = 0; t < T_; t++) a += tf[(b*T_ + t)*KB_ + k];
            sst[k][b] = a * (1.0f / T_);
        }
        __syncthreads();

        const int co = wi >> 2;
        const int q  = wi & 3;                // ci quarter (32 ci)
        const bool act = tid < 200;
        const float* src = Wb + co*3200 + q*800 + 4*tid;

        unsigned long long accp[8][4];        // [b-pair][component]
        #pragma unroll
        for (int i = 0; i < 8; i++)
            #pragma unroll
            for (int c = 0; c < 4; c++) accp[i][c] = 0ull;

        if (act) {
            #pragma unroll 1
            for (int k0 = 0; k0 < KB_; k0 += 4) {
                float4 wv[4];                 // 4 front-batched LDG.128
                #pragma unroll
                for (int j = 0; j < 4; j++)
                    wv[j] = *(const float4*)(src + (size_t)(k0 + j)*WELEMS);
                #pragma unroll
                for (int j = 0; j < 4; j++) {
                    unsigned long long wx = packdup(wv[j].x), wy = packdup(wv[j].y);
                    unsigned long long wz = packdup(wv[j].z), ww = packdup(wv[j].w);
                    const unsigned long long* sp =
                        (const unsigned long long*)&sst[k0 + j][0];
                    #pragma unroll
                    for (int i = 0; i < 8; i++) {
                        unsigned long long s2 = sp[i];
                        accp[i][0] = ffma2(s2, wx, accp[i][0]);
                        accp[i][1] = ffma2(s2, wy, accp[i][1]);
                        accp[i][2] = ffma2(s2, wz, accp[i][2]);
                        accp[i][3] = ffma2(s2, ww, accp[i][3]);
                    }
                }
            }
        }

        const int bsel  = tid / 100;
        const int t2    = tid % 100;
        const int tap   = t2 % 25;
        const int c8    = t2 / 25;            // ci8-block within quarter
        const int chunk = 2*q + (c8 >> 1);
        const int kk    = c8 & 1;
        const int coh   = co >> 6;
        const int c64   = co & 63;
        #pragma unroll 1
        for (int bp = 0; bp < 8; bp++) {
            if (act) {
                float4 a0, a1;
                unpack2(a0.x, a1.x, accp[bp][0]);
                unpack2(a0.y, a1.y, accp[bp][1]);
                unpack2(a0.z, a1.z, accp[bp][2]);
                unpack2(a0.w, a1.w, accp[bp][3]);
                *(float4*)(wbuf[0] + 4*tid) = a0;
                *(float4*)(wbuf[1] + 4*tid) = a1;
            }
            __syncthreads();
            if (tid < 200) {
                __half h[8];
                #pragma unroll
                for (int i2 = 0; i2 < 8; i2++)
                    h[i2] = __float2half_rn(wbuf[bsel][(c8*8 + i2)*25 + tap]);
                int b = 2*bp + bsel;
                size_t o = (((size_t)(b*8 + chunk)*2 + coh)*25600)
                         + (((size_t)kk*64 + c64)*25 + tap)*8;
                *(uint4*)(g_lphB + o) = *(const uint4*)h;
            }
            __syncthreads();
        }
    } else {
        // ---------------- xcvt: write padded planes (interior only) --------
        const int xi = blk >> 3;              // 0..73
        const size_t total4 = (size_t)B_*64*H_*W_ / 4;
        #pragma unroll 2
        for (size_t e = (size_t)xi*256 + tid; e < total4;
             e += (size_t)NXB*256) {
            size_t i = e * 4;
            int px   = (int)(i & 63);
            int rest = (int)(i >> 6);
            int h    = rest & 63;
            int pr   = rest >> 6;
            int pl   = pr & 63;
            int b    = pr >> 6;
            const float* xb = x + ((size_t)(b*CI_ + 2*pl)*H_ + h)*W_ + px;
            float4 lo = *(const float4*)xb;
            float4 hi = *(const float4*)(xb + H_*W_);
            uint4 o;
            __half2 p0 = __floats2half2_rn(lo.x, hi.x);
            __half2 p1 = __floats2half2_rn(lo.y, hi.y);
            __half2 p2 = __floats2half2_rn(lo.z, hi.z);
            __half2 p3 = __floats2half2_rn(lo.w, hi.w);
            o.x = *(unsigned*)&p0; o.y = *(unsigned*)&p1;
            o.z = *(unsigned*)&p2; o.w = *(unsigned*)&p3;
            size_t dst = ((size_t)(b*64 + pl)*68 + h + 2)*72 + px + 4;
            *(uint4*)(g_xh + dst) = o;
        }
    }
}

// ---------------------------------------------------------------------------
// Kernel C: fp16 m16n8k16 conv, double-buffered cp.async.bulk pipeline with
// full/empty mbarriers. 512 thr, 1 CTA/SM. Tile 64co x (8 rows x 64 px).
// (unchanged — proven at ~126 us)
// ---------------------------------------------------------------------------
#define WS0_OFF   1024
#define WS_BYTES  51200
#define XS0_OFF   (WS0_OFF + 2*WS_BYTES)          // 103424
#define XS_PLANE  872                             // words per plane (12*72 + 8)
#define XS_BYTES  (8*XS_PLANE*4)                  // 27904
#define SMEM_BYTES (XS0_OFF + 2*XS_BYTES)         // 159232
#define TX_BYTES  (WS_BYTES + 8*3456)             // 78848

__device__ __forceinline__ void bulk(unsigned dst, const void* src, unsigned n, unsigned mb) {
    asm volatile("cp.async.bulk.shared::cta.global.mbarrier::complete_tx::bytes [%0], [%1], %2, [%3];"
                 :: "r"(dst), "l"(src), "r"(n), "r"(mb) : "memory");
}
__device__ __forceinline__ void mbwait(unsigned mb, unsigned par) {
    asm volatile("{\n\t.reg .pred P;\n\tWL%=:\n\t"
                 "mbarrier.try_wait.parity.acquire.cta.shared::cta.b64 P, [%0], %1, 0x989680;\n\t"
                 "@P bra.uni WD%=;\n\tbra.uni WL%=;\n\tWD%=:\n\t}"
                 :: "r"(mb), "r"(par) : "memory");
}
__device__ __forceinline__ void mbarrive(unsigned mb) {
    asm volatile("mbarrier.arrive.shared.b64 _, [%0];" :: "r"(mb) : "memory");
}
__device__ __forceinline__ void ldsm4(unsigned* r, unsigned addr) {
    asm volatile("ldmatrix.sync.aligned.m8n8.x4.shared.b16 {%0,%1,%2,%3}, [%4];"
                 : "=r"(r[0]), "=r"(r[1]), "=r"(r[2]), "=r"(r[3]) : "r"(addr));
}
__device__ __forceinline__ void mma16(float* d, const unsigned* a, const unsigned* bb) {
    asm volatile("mma.sync.aligned.m16n8k16.row.col.f32.f16.f16.f32 "
                 "{%0,%1,%2,%3}, {%4,%5,%6,%7}, {%8,%9}, {%0,%1,%2,%3};"
                 : "+f"(d[0]), "+f"(d[1]), "+f"(d[2]), "+f"(d[3])
                 : "r"(a[0]), "r"(a[1]), "r"(a[2]), "r"(a[3]), "r"(bb[0]), "r"(bb[1]));
}

__global__ __launch_bounds__(512, 1) void k_conv(float* __restrict__ y) {
    extern __shared__ __align__(128) unsigned char smem[];
    const unsigned sb = (unsigned)__cvta_generic_to_shared(smem);

    const int tid = threadIdx.x;
    const int ln  = tid & 31;
    const int w   = tid >> 5;
    const int g   = ln >> 2;
    const int tig = ln & 3;
    const int wr  = w >> 1;
    const int cw  = (w & 1) * 32;

    const int h0  = blockIdx.x * 8;
    const int coh = blockIdx.y;
    const int b   = blockIdx.z;

    const unsigned aLane = ((unsigned)((ln >> 4)*64 + (ln & 15)))*400u;

    if (tid == 0) {
        asm volatile("mbarrier.init.shared.b64 [%0], 1;"   :: "r"(sb+0)  : "memory");
        asm volatile("mbarrier.init.shared.b64 [%0], 1;"   :: "r"(sb+8)  : "memory");
        asm volatile("mbarrier.init.shared.b64 [%0], 512;" :: "r"(sb+16) : "memory");
        asm volatile("mbarrier.init.shared.b64 [%0], 512;" :: "r"(sb+24) : "memory");
    }
    __syncthreads();

    auto stage = [&](int cs, int bufi) {
        unsigned mb = sb + bufi*8;
        asm volatile("mbarrier.arrive.expect_tx.shared.b64 _, [%0], %1;"
                     :: "r"(mb), "r"((unsigned)TX_BYTES) : "memory");
        bulk(sb + WS0_OFF + bufi*WS_BYTES,
             g_lphB + ((size_t)(b*8 + cs)*2 + coh)*25600, WS_BYTES, mb);
        #pragma unroll
        for (int pl = 0; pl < 8; pl++)
            bulk(sb + XS0_OFF + bufi*XS_BYTES + pl*(XS_PLANE*4),
                 g_xh + ((size_t)(b*64 + cs*8 + pl)*68 + h0)*72,
                 3456, mb);
    };

    float acc[4][4][4];
    #pragma unroll
    for (int mf = 0; mf < 4; mf++)
        #pragma unroll
        for (int f = 0; f < 4; f++)
            #pragma unroll
            for (int r = 0; r < 4; r++) acc[mf][f][r] = 0.f;

    if (tid == 0) { stage(0, 0); stage(1, 1); }

    #pragma unroll 1
    for (int cc = 0; cc < 8; cc++) {
        const int bufi = cc & 1;
        mbwait(sb + bufi*8, (cc >> 1) & 1);

        const unsigned  aBase = sb + WS0_OFF + bufi*WS_BYTES + aLane;
        const unsigned* XS    = (const unsigned*)(smem + XS0_OFF + bufi*XS_BYTES);
        const int xbase = wr*72 + 2 + cw + g;

        #pragma unroll
        for (int dh = 0; dh < 5; dh++) {
            #pragma unroll
            for (int dw = 0; dw < 5; dw++) {
                const int tap = dh*5 + dw;
                unsigned a[4][4];
                #pragma unroll
                for (int mf = 0; mf < 4; mf++)
                    ldsm4(a[mf], aBase + mf*6400 + tap*16);

                unsigned bb[4][2];
                const int xo = xbase + dh*72 + dw;
                #pragma unroll
                for (int f = 0; f < 4; f++) {
                    bb[f][0] = XS[tig*XS_PLANE       + xo + 8*f];
                    bb[f][1] = XS[(tig + 4)*XS_PLANE + xo + 8*f];
                }
                #pragma unroll
                for (int mf = 0; mf < 4; mf++)
                    #pragma unroll
                    for (int f = 0; f < 4; f++)
                        mma16(acc[mf][f], a[mf], bb[f]);
            }
        }

        mbarrive(sb + 16 + bufi*8);
        if (cc < 6 && tid == 0) {
            mbwait(sb + 16 + bufi*8, (cc >> 1) & 1);
            stage(cc + 2, bufi);
        }
    }

    const int hw = h0 + wr;
    #pragma unroll
    for (int mf = 0; mf < 4; mf++) {
        #pragma unroll
        for (int f = 0; f < 4; f++) {
            int co = coh*64 + 16*mf + g;
            int px = cw + 8*f + 2*tig;
            float* yp = y + (((size_t)b*CO_ + co)*H_ + hw)*W_ + px;
            *(float2*)yp             = make_float2(acc[mf][f][0], acc[mf][f][1]);
            *(float2*)(yp + 8*H_*W_) = make_float2(acc[mf][f][2], acc[mf][f][3]);
        }
    }
}

// ---------------------------------------------------------------------------
// Launch
// ---------------------------------------------------------------------------
extern "C" void kernel_launch(void* const* d_in, const int* in_sizes, int n_in,
                              void* d_out, int out_size) {
    const float* x  = (const float*)d_in[0];
    const float* tf = (const float*)d_in[1];
    const float* Wb = (const float*)d_in[2];
    float* y        = (float*)d_out;

    cudaFuncSetAttribute(k_conv, cudaFuncAttributeMaxDynamicSharedMemorySize, SMEM_BYTES);

    k_prep<<<NPREP, 256>>>(x, tf, Wb);
    dim3 grid(8, 2, B_);
    k_conv<<<grid, 512, SMEM_BYTES>>>(y);
    (void)in_sizes; (void)n_in; (void)out_size;
}